// round 13
// baseline (speedup 1.0000x reference)
#include <cuda_runtime.h>
#include <cstdint>

#define NN 100000
#define EE 1600000
#define DD 64
#define EPS 1e-5f

#define NBLK 98                       // ceil(NN/1024)
#define NN_PAD (NBLK * 1024)          // 100352

// ---------------- device scratch (no allocations allowed) ----------------
__device__ __align__(16) int   g_deg[NN_PAD];      // zero-init; re-zeroed by k_bscan_fill each launch
__device__ __align__(16) float g_dinv[NN_PAD];     // rsqrt(deg+1)
__device__ __align__(16) int   g_off[NN_PAD];      // CSR offsets
__device__ __align__(16) int   g_cursor[NN_PAD];   // fill cursors
__device__                int   g_bsum[NBLK];
__device__                int   g_bpre[NBLK];
__device__ __align__(8)  int2  g_edge[EE];         // (src, float-bits weight)
__device__ __align__(16) float g_hw[NN * DD];      // h @ W buffer
__device__ __align__(16) float g_h[NN * DD];       // intermediate h buffer

// ---------------- CSR build ----------------
__global__ __launch_bounds__(256) void k_count(const int* __restrict__ ei) {
    int e = blockIdx.x * blockDim.x + threadIdx.x;
    if (e < EE) atomicAdd(&g_deg[ei[EE + e]], 1);
}

__global__ __launch_bounds__(256) void k_bsum() {
    const int t = threadIdx.x, b = blockIdx.x;
    const int4* d4 = (const int4*)g_deg;
    int4 v = d4[b * 256 + t];
    int s = v.x + v.y + v.z + v.w;
#pragma unroll
    for (int m = 16; m; m >>= 1) s += __shfl_xor_sync(0xffffffffu, s, m);
    __shared__ int ws[8];
    if ((t & 31) == 0) ws[t >> 5] = s;
    __syncthreads();
    if (t == 0) {
        int x = 0;
#pragma unroll
        for (int i = 0; i < 8; i++) x += ws[i];
        g_bsum[b] = x;
    }
}

__global__ __launch_bounds__(128) void k_bscan() {
    __shared__ int s[128];
    const int t = threadIdx.x;
    int v = (t < NBLK) ? g_bsum[t] : 0;
    s[t] = v;
    __syncthreads();
    for (int off = 1; off < 128; off <<= 1) {
        int u = (t >= off) ? s[t - off] : 0;
        __syncthreads();
        s[t] += u;
        __syncthreads();
    }
    if (t < NBLK) g_bpre[t] = s[t] - v;  // exclusive
}

// writes g_off, g_cursor, g_dinv; re-zeroes g_deg for the next launch
__global__ __launch_bounds__(256) void k_bscan_fill() {
    const int t = threadIdx.x, b = blockIdx.x;
    const int lane = t & 31, wid = t >> 5;
    const int4* d4 = (const int4*)g_deg;
    int4 c = d4[b * 256 + t];
    int sum4 = c.x + c.y + c.z + c.w;

    int inc = sum4;
#pragma unroll
    for (int m = 1; m < 32; m <<= 1) {
        int u = __shfl_up_sync(0xffffffffu, inc, m);
        if (lane >= m) inc += u;
    }
    __shared__ int wsum[8], wpre[8];
    if (lane == 31) wsum[wid] = inc;
    __syncthreads();
    if (t == 0) {
        int r = 0;
#pragma unroll
        for (int i = 0; i < 8; i++) { wpre[i] = r; r += wsum[i]; }
    }
    __syncthreads();

    int excl = inc - sum4 + wpre[wid] + g_bpre[b];
    int o0 = excl, o1 = o0 + c.x, o2 = o1 + c.y, o3 = o2 + c.z;
    int4 off4 = make_int4(o0, o1, o2, o3);
    ((int4*)g_off)[b * 256 + t] = off4;
    ((int4*)g_cursor)[b * 256 + t] = off4;
    float4 dv;
    dv.x = rsqrtf((float)(c.x + 1));
    dv.y = rsqrtf((float)(c.y + 1));
    dv.z = rsqrtf((float)(c.z + 1));
    dv.w = rsqrtf((float)(c.w + 1));
    ((float4*)g_dinv)[b * 256 + t] = dv;
    ((int4*)g_deg)[b * 256 + t] = make_int4(0, 0, 0, 0);  // reset for next replay
}

__global__ __launch_bounds__(256) void k_fill(const int* __restrict__ ei) {
    int e = blockIdx.x * blockDim.x + threadIdx.x;
    if (e < EE) {
        int r = ei[e];
        int c = ei[EE + e];
        int p = atomicAdd(&g_cursor[c], 1);
        float w = g_dinv[r] * g_dinv[c];
        g_edge[p] = make_int2(r, __float_as_int(w));
    }
}

// ---------------- GEMM: hw = hin @ W via 3xTF32 mma.sync ----------------
// 256 threads = 8 warps; block does 128 rows; warp: 16 rows x 64 cols.
// W split hi/lo and pre-packed in fragment order -> conflict-free LDS.
__device__ __forceinline__ uint32_t f2tf32(float x) {
    uint32_t r;
    asm("cvt.rna.tf32.f32 %0, %1;" : "=r"(r) : "f"(x));
    return r;
}

__global__ __launch_bounds__(256) void k_gemm(const float* __restrict__ hin,
                                              const float* __restrict__ W,
                                              float* __restrict__ hout) {
    // fragment-packed W: [kstep][ntile][half*32 + lane]
    __shared__ uint32_t sBhi[8][8][64];
    __shared__ uint32_t sBlo[8][8][64];

    const int t = threadIdx.x;
    for (int i = t; i < 4096; i += 256) {
        int lane = i & 31;
        int half = (i >> 5) & 1;
        int ntile = (i >> 6) & 7;
        int kstep = i >> 9;
        int k = kstep * 8 + (lane & 3) + half * 4;
        int n = ntile * 8 + (lane >> 2);
        float w = W[k * 64 + n];
        uint32_t whi_b = f2tf32(w);
        float wlo = w - __uint_as_float(whi_b);
        sBhi[kstep][ntile][half * 32 + lane] = whi_b;
        sBlo[kstep][ntile][half * 32 + lane] = f2tf32(wlo);
    }
    __syncthreads();

    const int warp = t >> 5, lane = t & 31;
    const int gid = lane >> 2;          // 0..7
    const int tig = lane & 3;           // 0..3
    const int row0 = blockIdx.x * 128 + warp * 16 + gid;
    const int row1 = row0 + 8;
    const bool ok0 = row0 < NN, ok1 = row1 < NN;

    float d[8][4];
#pragma unroll
    for (int nt = 0; nt < 8; nt++) {
        d[nt][0] = 0.f; d[nt][1] = 0.f; d[nt][2] = 0.f; d[nt][3] = 0.f;
    }

#pragma unroll
    for (int ks = 0; ks < 8; ks++) {
        const int c0 = ks * 8 + tig;
        float av0 = ok0 ? __ldg(&hin[row0 * 64 + c0]) : 0.f;
        float av1 = ok1 ? __ldg(&hin[row1 * 64 + c0]) : 0.f;
        float av2 = ok0 ? __ldg(&hin[row0 * 64 + c0 + 4]) : 0.f;
        float av3 = ok1 ? __ldg(&hin[row1 * 64 + c0 + 4]) : 0.f;

        uint32_t ah0 = f2tf32(av0), ah1 = f2tf32(av1), ah2 = f2tf32(av2), ah3 = f2tf32(av3);
        uint32_t al0 = f2tf32(av0 - __uint_as_float(ah0));
        uint32_t al1 = f2tf32(av1 - __uint_as_float(ah1));
        uint32_t al2 = f2tf32(av2 - __uint_as_float(ah2));
        uint32_t al3 = f2tf32(av3 - __uint_as_float(ah3));

#pragma unroll
        for (int nt = 0; nt < 8; nt++) {
            uint32_t bh0 = sBhi[ks][nt][lane];
            uint32_t bh1 = sBhi[ks][nt][32 + lane];
            uint32_t bl0 = sBlo[ks][nt][lane];
            uint32_t bl1 = sBlo[ks][nt][32 + lane];
            asm("mma.sync.aligned.m16n8k8.row.col.f32.tf32.tf32.f32 "
                "{%0,%1,%2,%3}, {%4,%5,%6,%7}, {%8,%9}, {%0,%1,%2,%3};"
                : "+f"(d[nt][0]), "+f"(d[nt][1]), "+f"(d[nt][2]), "+f"(d[nt][3])
                : "r"(ah0), "r"(ah1), "r"(ah2), "r"(ah3), "r"(bh0), "r"(bh1));
            asm("mma.sync.aligned.m16n8k8.row.col.f32.tf32.tf32.f32 "
                "{%0,%1,%2,%3}, {%4,%5,%6,%7}, {%8,%9}, {%0,%1,%2,%3};"
                : "+f"(d[nt][0]), "+f"(d[nt][1]), "+f"(d[nt][2]), "+f"(d[nt][3])
                : "r"(ah0), "r"(ah1), "r"(ah2), "r"(ah3), "r"(bl0), "r"(bl1));
            asm("mma.sync.aligned.m16n8k8.row.col.f32.tf32.tf32.f32 "
                "{%0,%1,%2,%3}, {%4,%5,%6,%7}, {%8,%9}, {%0,%1,%2,%3};"
                : "+f"(d[nt][0]), "+f"(d[nt][1]), "+f"(d[nt][2]), "+f"(d[nt][3])
                : "r"(al0), "r"(al1), "r"(al2), "r"(al3), "r"(bh0), "r"(bh1));
        }
    }

    // store: c0/c1 -> (row0, n0+2*tig .. +1), c2/c3 -> (row1, same cols)
#pragma unroll
    for (int nt = 0; nt < 8; nt++) {
        int cn = nt * 8 + 2 * tig;
        if (ok0) *(float2*)&hout[row0 * 64 + cn] = make_float2(d[nt][0], d[nt][1]);
        if (ok1) *(float2*)&hout[row1 * 64 + cn] = make_float2(d[nt][2], d[nt][3]);
    }
}

// ---------------- fused aggregate + bias + LayerNorm (+ReLU) ----------------
// 16 lanes per node; meta batches of 16 edges, software-pipelined (prefetch next)
__global__ __launch_bounds__(256) void k_agg(const float* __restrict__ hw,
                                             const float* __restrict__ bias,
                                             const float* __restrict__ gamma,
                                             const float* __restrict__ beta,
                                             float* __restrict__ out,
                                             int do_relu) {
    const int t = threadIdx.x;
    const int node = blockIdx.x * 16 + (t >> 4);   // NN % 16 == 0
    const int j = t & 15;
    const unsigned gmask = 0xffffu << (t & 16);

    const float4* hw4 = (const float4*)hw;

    // self-loop term
    float dn = g_dinv[node];
    float4 acc = hw4[node * 16 + j];
    float wself = dn * dn;
    acc.x *= wself; acc.y *= wself; acc.z *= wself; acc.w *= wself;

    int p = g_off[node];
    const int pend = g_off[node + 1];

    // pipelined full batches of 16 edges
    int2 e = make_int2(0, 0);
    bool have = (p + 16 <= pend);
    if (have) e = __ldg(&g_edge[p + j]);
    while (have) {
        int2 cur = e;
        p += 16;
        have = (p + 16 <= pend);
        if (have) e = __ldg(&g_edge[p + j]);   // prefetch next batch
#pragma unroll
        for (int i = 0; i < 16; i++) {
            int src = __shfl_sync(gmask, cur.x, i, 16);
            float w = __int_as_float(__shfl_sync(gmask, cur.y, i, 16));
            float4 v = hw4[src * 16 + j];
            acc.x += w * v.x;
            acc.y += w * v.y;
            acc.z += w * v.z;
            acc.w += w * v.w;
        }
    }
    // remainder (0..15 edges)
    int rem = pend - p;
    if (rem > 0) {
        int2 er = make_int2(0, 0);
        if (j < rem) er = __ldg(&g_edge[p + j]);
        for (int i = 0; i < rem; i++) {
            int src = __shfl_sync(gmask, er.x, i, 16);
            float w = __int_as_float(__shfl_sync(gmask, er.y, i, 16));
            float4 v = hw4[src * 16 + j];
            acc.x += w * v.x;
            acc.y += w * v.y;
            acc.z += w * v.z;
            acc.w += w * v.w;
        }
    }

    float4 b = ((const float4*)bias)[j];
    acc.x += b.x; acc.y += b.y; acc.z += b.z; acc.w += b.w;

    // LayerNorm over 64 values (16 lanes x 4)
    float lsum = acc.x + acc.y + acc.z + acc.w;
    float lsq  = acc.x * acc.x + acc.y * acc.y + acc.z * acc.z + acc.w * acc.w;
#pragma unroll
    for (int m = 8; m >= 1; m >>= 1) {
        lsum += __shfl_xor_sync(gmask, lsum, m, 16);
        lsq  += __shfl_xor_sync(gmask, lsq,  m, 16);
    }
    float mean = lsum * (1.0f / 64.0f);
    float var = lsq * (1.0f / 64.0f) - mean * mean;
    float rstd = rsqrtf(var + EPS);

    float4 g = ((const float4*)gamma)[j];
    float4 be = ((const float4*)beta)[j];
    float4 o;
    o.x = (acc.x - mean) * rstd * g.x + be.x;
    o.y = (acc.y - mean) * rstd * g.y + be.y;
    o.z = (acc.z - mean) * rstd * g.z + be.z;
    o.w = (acc.w - mean) * rstd * g.w + be.w;
    if (do_relu) {
        o.x = fmaxf(o.x, 0.f);
        o.y = fmaxf(o.y, 0.f);
        o.z = fmaxf(o.z, 0.f);
        o.w = fmaxf(o.w, 0.f);
    }
    ((float4*)out)[node * 16 + j] = o;
}

// ---------------- launch ----------------
extern "C" void kernel_launch(void* const* d_in, const int* in_sizes, int n_in,
                              void* d_out, int out_size) {
    const float* x      = (const float*)d_in[0];   // (N, D)
    const float* Ws     = (const float*)d_in[1];   // (L, D, D)
    const float* bs     = (const float*)d_in[2];   // (L, D)
    const float* gammas = (const float*)d_in[3];   // (L, D)
    const float* betas  = (const float*)d_in[4];   // (L, D)
    const int*   ei     = (const int*)d_in[5];     // (2, E)
    float* outp = (float*)d_out;

    float* d_hw;
    float* d_h;
    cudaGetSymbolAddress((void**)&d_hw, g_hw);
    cudaGetSymbolAddress((void**)&d_h, g_h);

    const int TB = 256;
    const int gE = (EE + TB - 1) / TB;
    const int gGemm = (NN + 127) / 128;
    const int gAgg = NN / 16;

    // CSR build (g_deg zeroed at module load / by previous replay)
    k_count<<<gE, TB>>>(ei);
    k_bsum<<<NBLK, 256>>>();
    k_bscan<<<1, 128>>>();
    k_bscan_fill<<<NBLK, 256>>>();
    k_fill<<<gE, TB>>>(ei);

    // layer 0: x -> g_h
    k_gemm<<<gGemm, TB>>>(x, Ws + 0 * DD * DD, d_hw);
    k_agg<<<gAgg, TB>>>(d_hw, bs + 0 * DD, gammas + 0 * DD, betas + 0 * DD, d_h, 1);
    // layer 1
    k_gemm<<<gGemm, TB>>>(d_h, Ws + 1 * DD * DD, d_hw);
    k_agg<<<gAgg, TB>>>(d_hw, bs + 1 * DD, gammas + 1 * DD, betas + 1 * DD, d_h, 1);
    // layer 2 (no relu)
    k_gemm<<<gGemm, TB>>>(d_h, Ws + 2 * DD * DD, d_hw);
    k_agg<<<gAgg, TB>>>(d_hw, bs + 2 * DD, gammas + 2 * DD, betas + 2 * DD, outp, 0);
}

// round 15
// speedup vs baseline: 1.2191x; 1.2191x over previous
#include <cuda_runtime.h>
#include <cuda_fp16.h>

#define NN 100000
#define EE 1600000
#define DD 64
#define EPS 1e-5f

#define NBLK 98                       // ceil(NN/1024)
#define NN_PAD (NBLK * 1024)          // 100352

// ---------------- device scratch (no allocations allowed) ----------------
__device__ __align__(16) int    g_deg[NN_PAD];     // zero-init; re-zeroed by k_bscan_fill each launch
__device__ __align__(16) float  g_dinv[NN_PAD];    // rsqrt(deg+1)
__device__ __align__(16) int    g_off[NN_PAD];     // CSR offsets
__device__ __align__(16) int    g_cursor[NN_PAD];  // fill cursors
__device__                int    g_bsum[NBLK];
__device__                int    g_bpre[NBLK];
__device__ __align__(8)  int2   g_edge[EE];        // (src, float-bits weight)
__device__ __align__(16) __half g_hw[NN * DD];     // h @ W buffer (fp16: halves gather traffic)
__device__ __align__(16) float  g_h[NN * DD];      // intermediate h buffer (fp32)

// ---------------- CSR build ----------------
__global__ __launch_bounds__(256) void k_count(const int* __restrict__ ei) {
    int e = blockIdx.x * blockDim.x + threadIdx.x;
    if (e < EE) atomicAdd(&g_deg[ei[EE + e]], 1);
}

__global__ __launch_bounds__(256) void k_bsum() {
    const int t = threadIdx.x, b = blockIdx.x;
    const int4* d4 = (const int4*)g_deg;
    int4 v = d4[b * 256 + t];
    int s = v.x + v.y + v.z + v.w;
#pragma unroll
    for (int m = 16; m; m >>= 1) s += __shfl_xor_sync(0xffffffffu, s, m);
    __shared__ int ws[8];
    if ((t & 31) == 0) ws[t >> 5] = s;
    __syncthreads();
    if (t == 0) {
        int x = 0;
#pragma unroll
        for (int i = 0; i < 8; i++) x += ws[i];
        g_bsum[b] = x;
    }
}

__global__ __launch_bounds__(128) void k_bscan() {
    __shared__ int s[128];
    const int t = threadIdx.x;
    int v = (t < NBLK) ? g_bsum[t] : 0;
    s[t] = v;
    __syncthreads();
    for (int off = 1; off < 128; off <<= 1) {
        int u = (t >= off) ? s[t - off] : 0;
        __syncthreads();
        s[t] += u;
        __syncthreads();
    }
    if (t < NBLK) g_bpre[t] = s[t] - v;  // exclusive
}

// writes g_off, g_cursor, g_dinv; re-zeroes g_deg for the next launch
__global__ __launch_bounds__(256) void k_bscan_fill() {
    const int t = threadIdx.x, b = blockIdx.x;
    const int lane = t & 31, wid = t >> 5;
    const int4* d4 = (const int4*)g_deg;
    int4 c = d4[b * 256 + t];
    int sum4 = c.x + c.y + c.z + c.w;

    int inc = sum4;
#pragma unroll
    for (int m = 1; m < 32; m <<= 1) {
        int u = __shfl_up_sync(0xffffffffu, inc, m);
        if (lane >= m) inc += u;
    }
    __shared__ int wsum[8], wpre[8];
    if (lane == 31) wsum[wid] = inc;
    __syncthreads();
    if (t == 0) {
        int r = 0;
#pragma unroll
        for (int i = 0; i < 8; i++) { wpre[i] = r; r += wsum[i]; }
    }
    __syncthreads();

    int excl = inc - sum4 + wpre[wid] + g_bpre[b];
    int o0 = excl, o1 = o0 + c.x, o2 = o1 + c.y, o3 = o2 + c.z;
    int4 off4 = make_int4(o0, o1, o2, o3);
    ((int4*)g_off)[b * 256 + t] = off4;
    ((int4*)g_cursor)[b * 256 + t] = off4;
    float4 dv;
    dv.x = rsqrtf((float)(c.x + 1));
    dv.y = rsqrtf((float)(c.y + 1));
    dv.z = rsqrtf((float)(c.z + 1));
    dv.w = rsqrtf((float)(c.w + 1));
    ((float4*)g_dinv)[b * 256 + t] = dv;
    ((int4*)g_deg)[b * 256 + t] = make_int4(0, 0, 0, 0);  // reset for next replay
}

__global__ __launch_bounds__(256) void k_fill(const int* __restrict__ ei) {
    int e = blockIdx.x * blockDim.x + threadIdx.x;
    if (e < EE) {
        int r = ei[e];
        int c = ei[EE + e];
        int p = atomicAdd(&g_cursor[c], 1);
        float w = g_dinv[r] * g_dinv[c];
        g_edge[p] = make_int2(r, __float_as_int(w));
    }
}

// ---------------- GEMM: hw = hin @ W (N x 64 @ 64 x 64), fp16 output ----------------
// 64 rows per block of 256 threads; each thread: 4 rows x 4 cols register tile
__global__ __launch_bounds__(256) void k_gemm(const float* __restrict__ hin,
                                              const float* __restrict__ W,
                                              __half* __restrict__ hout) {
    __shared__ float4 sW[64 * 16];     // W[k][j4]
    __shared__ float  sH[64][68];      // 68-pad: kills half-warp row bank conflict

    const int t = threadIdx.x;
    const float4* W4 = (const float4*)W;
#pragma unroll
    for (int i = 0; i < 4; i++) sW[t + i * 256] = W4[t + i * 256];

    const int rowbase = blockIdx.x * 64;
    const float4* hin4 = (const float4*)hin;
#pragma unroll
    for (int i = 0; i < 4; i++) {
        int idx = t + i * 256;          // 0..1023
        int r = idx >> 4, c = idx & 15;
        float4 v = make_float4(0.f, 0.f, 0.f, 0.f);
        if (rowbase + r < NN) v = hin4[(rowbase + r) * 16 + c];
        ((float4*)&sH[r][0])[c] = v;
    }
    __syncthreads();

    const int j = t & 15;       // col group (4 cols)
    const int rg = t >> 4;      // rows rg, rg+16, rg+32, rg+48

    float4 a0 = make_float4(0.f, 0.f, 0.f, 0.f);
    float4 a1 = a0, a2 = a0, a3 = a0;
#pragma unroll 16
    for (int k = 0; k < 64; k++) {
        float4 w = sW[k * 16 + j];
        float h0 = sH[rg][k];
        float h1 = sH[rg + 16][k];
        float h2 = sH[rg + 32][k];
        float h3 = sH[rg + 48][k];
        a0.x += h0 * w.x; a0.y += h0 * w.y; a0.z += h0 * w.z; a0.w += h0 * w.w;
        a1.x += h1 * w.x; a1.y += h1 * w.y; a1.z += h1 * w.z; a1.w += h1 * w.w;
        a2.x += h2 * w.x; a2.y += h2 * w.y; a2.z += h2 * w.z; a2.w += h2 * w.w;
        a3.x += h3 * w.x; a3.y += h3 * w.y; a3.z += h3 * w.z; a3.w += h3 * w.w;
    }

    uint2* hout2 = (uint2*)hout;       // 4 halfs per lane-group slot
    uint2 p;
    __half2 q0, q1;
    if (rowbase + rg < NN) {
        q0 = __floats2half2_rn(a0.x, a0.y); q1 = __floats2half2_rn(a0.z, a0.w);
        p.x = *(unsigned*)&q0; p.y = *(unsigned*)&q1;
        hout2[(rowbase + rg) * 16 + j] = p;
    }
    if (rowbase + rg + 16 < NN) {
        q0 = __floats2half2_rn(a1.x, a1.y); q1 = __floats2half2_rn(a1.z, a1.w);
        p.x = *(unsigned*)&q0; p.y = *(unsigned*)&q1;
        hout2[(rowbase + rg + 16) * 16 + j] = p;
    }
    if (rowbase + rg + 32 < NN) {
        q0 = __floats2half2_rn(a2.x, a2.y); q1 = __floats2half2_rn(a2.z, a2.w);
        p.x = *(unsigned*)&q0; p.y = *(unsigned*)&q1;
        hout2[(rowbase + rg + 32) * 16 + j] = p;
    }
    if (rowbase + rg + 48 < NN) {
        q0 = __floats2half2_rn(a3.x, a3.y); q1 = __floats2half2_rn(a3.z, a3.w);
        p.x = *(unsigned*)&q0; p.y = *(unsigned*)&q1;
        hout2[(rowbase + rg + 48) * 16 + j] = p;
    }
}

// ---------------- fused aggregate + bias + LayerNorm (+ReLU) ----------------
// 16 lanes per node; fp16 gather (8B/lane); meta batches of 16, pipelined
__global__ __launch_bounds__(256) void k_agg(const __half* __restrict__ hw,
                                             const float* __restrict__ bias,
                                             const float* __restrict__ gamma,
                                             const float* __restrict__ beta,
                                             float* __restrict__ out,
                                             int do_relu) {
    const int t = threadIdx.x;
    const int node = blockIdx.x * 16 + (t >> 4);   // NN % 16 == 0
    const int j = t & 15;
    const unsigned gmask = 0xffffu << (t & 16);

    const uint2* hw2 = (const uint2*)hw;

    // self-loop term
    float dn = g_dinv[node];
    uint2 sv = __ldg(&hw2[node * 16 + j]);
    __half2 sh0 = *(__half2*)&sv.x, sh1 = *(__half2*)&sv.y;
    float2 sf0 = __half22float2(sh0), sf1 = __half22float2(sh1);
    float wself = dn * dn;
    float4 acc;
    acc.x = sf0.x * wself; acc.y = sf0.y * wself;
    acc.z = sf1.x * wself; acc.w = sf1.y * wself;

    int p = g_off[node];
    const int pend = g_off[node + 1];

    // pipelined full batches of 16 edges
    int2 e = make_int2(0, 0);
    bool have = (p + 16 <= pend);
    if (have) e = __ldg(&g_edge[p + j]);
    while (have) {
        int2 cur = e;
        p += 16;
        have = (p + 16 <= pend);
        if (have) e = __ldg(&g_edge[p + j]);   // prefetch next batch
#pragma unroll
        for (int i = 0; i < 16; i++) {
            int src = __shfl_sync(gmask, cur.x, i, 16);
            float w = __int_as_float(__shfl_sync(gmask, cur.y, i, 16));
            uint2 v = __ldg(&hw2[src * 16 + j]);
            __half2 h0 = *(__half2*)&v.x, h1 = *(__half2*)&v.y;
            float2 f0 = __half22float2(h0), f1 = __half22float2(h1);
            acc.x += w * f0.x;
            acc.y += w * f0.y;
            acc.z += w * f1.x;
            acc.w += w * f1.y;
        }
    }
    // remainder (0..15 edges)
    int rem = pend - p;
    if (rem > 0) {
        int2 er = make_int2(0, 0);
        if (j < rem) er = __ldg(&g_edge[p + j]);
        for (int i = 0; i < rem; i++) {
            int src = __shfl_sync(gmask, er.x, i, 16);
            float w = __int_as_float(__shfl_sync(gmask, er.y, i, 16));
            uint2 v = __ldg(&hw2[src * 16 + j]);
            __half2 h0 = *(__half2*)&v.x, h1 = *(__half2*)&v.y;
            float2 f0 = __half22float2(h0), f1 = __half22float2(h1);
            acc.x += w * f0.x;
            acc.y += w * f0.y;
            acc.z += w * f1.x;
            acc.w += w * f1.y;
        }
    }

    float4 b = ((const float4*)bias)[j];
    acc.x += b.x; acc.y += b.y; acc.z += b.z; acc.w += b.w;

    // LayerNorm over 64 values (16 lanes x 4)
    float lsum = acc.x + acc.y + acc.z + acc.w;
    float lsq  = acc.x * acc.x + acc.y * acc.y + acc.z * acc.z + acc.w * acc.w;
#pragma unroll
    for (int m = 8; m >= 1; m >>= 1) {
        lsum += __shfl_xor_sync(gmask, lsum, m, 16);
        lsq  += __shfl_xor_sync(gmask, lsq,  m, 16);
    }
    float mean = lsum * (1.0f / 64.0f);
    float var = lsq * (1.0f / 64.0f) - mean * mean;
    float rstd = rsqrtf(var + EPS);

    float4 g = ((const float4*)gamma)[j];
    float4 be = ((const float4*)beta)[j];
    float4 o;
    o.x = (acc.x - mean) * rstd * g.x + be.x;
    o.y = (acc.y - mean) * rstd * g.y + be.y;
    o.z = (acc.z - mean) * rstd * g.z + be.z;
    o.w = (acc.w - mean) * rstd * g.w + be.w;
    if (do_relu) {
        o.x = fmaxf(o.x, 0.f);
        o.y = fmaxf(o.y, 0.f);
        o.z = fmaxf(o.z, 0.f);
        o.w = fmaxf(o.w, 0.f);
    }
    ((float4*)out)[node * 16 + j] = o;
}

// ---------------- launch ----------------
extern "C" void kernel_launch(void* const* d_in, const int* in_sizes, int n_in,
                              void* d_out, int out_size) {
    const float* x      = (const float*)d_in[0];   // (N, D)
    const float* Ws     = (const float*)d_in[1];   // (L, D, D)
    const float* bs     = (const float*)d_in[2];   // (L, D)
    const float* gammas = (const float*)d_in[3];   // (L, D)
    const float* betas  = (const float*)d_in[4];   // (L, D)
    const int*   ei     = (const int*)d_in[5];     // (2, E)
    float* outp = (float*)d_out;

    __half* d_hw;
    float*  d_h;
    cudaGetSymbolAddress((void**)&d_hw, g_hw);
    cudaGetSymbolAddress((void**)&d_h, g_h);

    const int TB = 256;
    const int gE = (EE + TB - 1) / TB;
    const int gGemm = (NN + 63) / 64;
    const int gAgg = NN / 16;

    // CSR build (g_deg zeroed at module load / by previous replay)
    k_count<<<gE, TB>>>(ei);
    k_bsum<<<NBLK, 256>>>();
    k_bscan<<<1, 128>>>();
    k_bscan_fill<<<NBLK, 256>>>();
    k_fill<<<gE, TB>>>(ei);

    // layer 0: x -> g_h
    k_gemm<<<gGemm, TB>>>(x, Ws + 0 * DD * DD, d_hw);
    k_agg<<<gAgg, TB>>>(d_hw, bs + 0 * DD, gammas + 0 * DD, betas + 0 * DD, d_h, 1);
    // layer 1
    k_gemm<<<gGemm, TB>>>(d_h, Ws + 1 * DD * DD, d_hw);
    k_agg<<<gAgg, TB>>>(d_hw, bs + 1 * DD, gammas + 1 * DD, betas + 1 * DD, d_h, 1);
    // layer 2 (no relu)
    k_gemm<<<gGemm, TB>>>(d_h, Ws + 2 * DD * DD, d_hw);
    k_agg<<<gAgg, TB>>>(d_hw, bs + 2 * DD, gammas + 2 * DD, betas + 2 * DD, outp, 0);
}

// round 16
// speedup vs baseline: 1.2441x; 1.0205x over previous
#include <cuda_runtime.h>
#include <cuda_fp16.h>

#define NN 100000
#define EE 1600000
#define DD 64
#define EPS 1e-5f

#define NBLK 98                       // ceil(NN/1024)
#define NN_PAD (NBLK * 1024)          // 100352
#define G_GEMM 1563                   // ceil(NN/64)
#define G_EDGE 6250                   // EE/256

// ---------------- device scratch (no allocations allowed) ----------------
__device__ __align__(16) int    g_deg[NN_PAD];     // zero-init; re-zeroed by k_bscan_fill each launch
__device__ __align__(16) float  g_dinv[NN_PAD];    // rsqrt(deg+1)
__device__ __align__(16) int    g_off[NN_PAD];     // CSR offsets
__device__ __align__(16) int    g_cursor[NN_PAD];  // fill cursors
__device__                int    g_bsum[NBLK];
__device__                int    g_bpre[NBLK];
__device__ __align__(8)  int2   g_edge[EE];        // (src, float-bits weight)
__device__ __align__(16) __half g_hw[NN * DD];     // h @ W buffer (fp16: halves gather traffic)
__device__ __align__(16) float  g_h[NN * DD];      // intermediate h buffer (fp32)

// ---------------- GEMM body (shared by fat kernel and standalone) ----------------
__device__ __forceinline__ void gemm_body(int blk, int t,
                                          const float* __restrict__ hin,
                                          const float* __restrict__ W,
                                          __half* __restrict__ hout,
                                          float4* sW, float (*sH)[68]) {
    const float4* W4 = (const float4*)W;
#pragma unroll
    for (int i = 0; i < 4; i++) sW[t + i * 256] = W4[t + i * 256];

    const int rowbase = blk * 64;
    const float4* hin4 = (const float4*)hin;
#pragma unroll
    for (int i = 0; i < 4; i++) {
        int idx = t + i * 256;          // 0..1023
        int r = idx >> 4, c = idx & 15;
        float4 v = make_float4(0.f, 0.f, 0.f, 0.f);
        if (rowbase + r < NN) v = hin4[(rowbase + r) * 16 + c];
        ((float4*)&sH[r][0])[c] = v;
    }
    __syncthreads();

    const int j = t & 15;       // col group (4 cols)
    const int rg = t >> 4;      // rows rg, rg+16, rg+32, rg+48

    float4 a0 = make_float4(0.f, 0.f, 0.f, 0.f);
    float4 a1 = a0, a2 = a0, a3 = a0;
#pragma unroll 16
    for (int k = 0; k < 64; k++) {
        float4 w = sW[k * 16 + j];
        float h0 = sH[rg][k];
        float h1 = sH[rg + 16][k];
        float h2 = sH[rg + 32][k];
        float h3 = sH[rg + 48][k];
        a0.x += h0 * w.x; a0.y += h0 * w.y; a0.z += h0 * w.z; a0.w += h0 * w.w;
        a1.x += h1 * w.x; a1.y += h1 * w.y; a1.z += h1 * w.z; a1.w += h1 * w.w;
        a2.x += h2 * w.x; a2.y += h2 * w.y; a2.z += h2 * w.z; a2.w += h2 * w.w;
        a3.x += h3 * w.x; a3.y += h3 * w.y; a3.z += h3 * w.z; a3.w += h3 * w.w;
    }

    uint2* hout2 = (uint2*)hout;
    uint2 p;
    __half2 q0, q1;
    if (rowbase + rg < NN) {
        q0 = __floats2half2_rn(a0.x, a0.y); q1 = __floats2half2_rn(a0.z, a0.w);
        p.x = *(unsigned*)&q0; p.y = *(unsigned*)&q1;
        hout2[(rowbase + rg) * 16 + j] = p;
    }
    if (rowbase + rg + 16 < NN) {
        q0 = __floats2half2_rn(a1.x, a1.y); q1 = __floats2half2_rn(a1.z, a1.w);
        p.x = *(unsigned*)&q0; p.y = *(unsigned*)&q1;
        hout2[(rowbase + rg + 16) * 16 + j] = p;
    }
    if (rowbase + rg + 32 < NN) {
        q0 = __floats2half2_rn(a2.x, a2.y); q1 = __floats2half2_rn(a2.z, a2.w);
        p.x = *(unsigned*)&q0; p.y = *(unsigned*)&q1;
        hout2[(rowbase + rg + 32) * 16 + j] = p;
    }
    if (rowbase + rg + 48 < NN) {
        q0 = __floats2half2_rn(a3.x, a3.y); q1 = __floats2half2_rn(a3.z, a3.w);
        p.x = *(unsigned*)&q0; p.y = *(unsigned*)&q1;
        hout2[(rowbase + rg + 48) * 16 + j] = p;
    }
}

// ---------------- fat kernel: layer-0 GEMM blocks + edge-count blocks ----------------
__global__ __launch_bounds__(256) void k_count_gemm0(const int* __restrict__ ei,
                                                     const float* __restrict__ x,
                                                     const float* __restrict__ W0,
                                                     __half* __restrict__ hw) {
    __shared__ float4 sW[64 * 16];
    __shared__ float  sH[64][68];
    const int t = threadIdx.x;
    if (blockIdx.x < G_GEMM) {
        gemm_body(blockIdx.x, t, x, W0, hw, sW, sH);
    } else {
        int e = (blockIdx.x - G_GEMM) * 256 + t;
        if (e < EE) atomicAdd(&g_deg[ei[EE + e]], 1);
    }
}

// ---------------- standalone GEMM (layers 1,2) ----------------
__global__ __launch_bounds__(256) void k_gemm(const float* __restrict__ hin,
                                              const float* __restrict__ W,
                                              __half* __restrict__ hout) {
    __shared__ float4 sW[64 * 16];
    __shared__ float  sH[64][68];
    gemm_body(blockIdx.x, threadIdx.x, hin, W, hout, sW, sH);
}

// ---------------- CSR build ----------------
__global__ __launch_bounds__(256) void k_bsum() {
    const int t = threadIdx.x, b = blockIdx.x;
    const int4* d4 = (const int4*)g_deg;
    int4 v = d4[b * 256 + t];
    int s = v.x + v.y + v.z + v.w;
#pragma unroll
    for (int m = 16; m; m >>= 1) s += __shfl_xor_sync(0xffffffffu, s, m);
    __shared__ int ws[8];
    if ((t & 31) == 0) ws[t >> 5] = s;
    __syncthreads();
    if (t == 0) {
        int x = 0;
#pragma unroll
        for (int i = 0; i < 8; i++) x += ws[i];
        g_bsum[b] = x;
    }
}

__global__ __launch_bounds__(128) void k_bscan() {
    __shared__ int s[128];
    const int t = threadIdx.x;
    int v = (t < NBLK) ? g_bsum[t] : 0;
    s[t] = v;
    __syncthreads();
    for (int off = 1; off < 128; off <<= 1) {
        int u = (t >= off) ? s[t - off] : 0;
        __syncthreads();
        s[t] += u;
        __syncthreads();
    }
    if (t < NBLK) g_bpre[t] = s[t] - v;  // exclusive
}

// writes g_off, g_cursor, g_dinv; re-zeroes g_deg for the next launch
__global__ __launch_bounds__(256) void k_bscan_fill() {
    const int t = threadIdx.x, b = blockIdx.x;
    const int lane = t & 31, wid = t >> 5;
    const int4* d4 = (const int4*)g_deg;
    int4 c = d4[b * 256 + t];
    int sum4 = c.x + c.y + c.z + c.w;

    int inc = sum4;
#pragma unroll
    for (int m = 1; m < 32; m <<= 1) {
        int u = __shfl_up_sync(0xffffffffu, inc, m);
        if (lane >= m) inc += u;
    }
    __shared__ int wsum[8], wpre[8];
    if (lane == 31) wsum[wid] = inc;
    __syncthreads();
    if (t == 0) {
        int r = 0;
#pragma unroll
        for (int i = 0; i < 8; i++) { wpre[i] = r; r += wsum[i]; }
    }
    __syncthreads();

    int excl = inc - sum4 + wpre[wid] + g_bpre[b];
    int o0 = excl, o1 = o0 + c.x, o2 = o1 + c.y, o3 = o2 + c.z;
    int4 off4 = make_int4(o0, o1, o2, o3);
    ((int4*)g_off)[b * 256 + t] = off4;
    ((int4*)g_cursor)[b * 256 + t] = off4;
    float4 dv;
    dv.x = rsqrtf((float)(c.x + 1));
    dv.y = rsqrtf((float)(c.y + 1));
    dv.z = rsqrtf((float)(c.z + 1));
    dv.w = rsqrtf((float)(c.w + 1));
    ((float4*)g_dinv)[b * 256 + t] = dv;
    ((int4*)g_deg)[b * 256 + t] = make_int4(0, 0, 0, 0);  // reset for next replay
}

__global__ __launch_bounds__(256) void k_fill(const int* __restrict__ ei) {
    int e = blockIdx.x * blockDim.x + threadIdx.x;
    if (e < EE) {
        int r = ei[e];
        int c = ei[EE + e];
        int p = atomicAdd(&g_cursor[c], 1);
        float w = g_dinv[r] * g_dinv[c];
        g_edge[p] = make_int2(r, __float_as_int(w));
    }
}

// ---------------- fused aggregate + bias + LayerNorm (+ReLU) ----------------
// 16 lanes per node; fp16 gather (8B/lane); meta batches of 16, pipelined
__global__ __launch_bounds__(256) void k_agg(const __half* __restrict__ hw,
                                             const float* __restrict__ bias,
                                             const float* __restrict__ gamma,
                                             const float* __restrict__ beta,
                                             float* __restrict__ out,
                                             int do_relu) {
    const int t = threadIdx.x;
    const int node = blockIdx.x * 16 + (t >> 4);   // NN % 16 == 0
    const int j = t & 15;
    const unsigned gmask = 0xffffu << (t & 16);

    const uint2* hw2 = (const uint2*)hw;

    // self-loop term
    float dn = g_dinv[node];
    uint2 sv = __ldg(&hw2[node * 16 + j]);
    __half2 sh0 = *(__half2*)&sv.x, sh1 = *(__half2*)&sv.y;
    float2 sf0 = __half22float2(sh0), sf1 = __half22float2(sh1);
    float wself = dn * dn;
    float4 acc;
    acc.x = sf0.x * wself; acc.y = sf0.y * wself;
    acc.z = sf1.x * wself; acc.w = sf1.y * wself;

    int p = g_off[node];
    const int pend = g_off[node + 1];

    // pipelined full batches of 16 edges
    int2 e = make_int2(0, 0);
    bool have = (p + 16 <= pend);
    if (have) e = __ldg(&g_edge[p + j]);
    while (have) {
        int2 cur = e;
        p += 16;
        have = (p + 16 <= pend);
        if (have) e = __ldg(&g_edge[p + j]);   // prefetch next batch
#pragma unroll
        for (int i = 0; i < 16; i++) {
            int src = __shfl_sync(gmask, cur.x, i, 16);
            float w = __int_as_float(__shfl_sync(gmask, cur.y, i, 16));
            uint2 v = __ldg(&hw2[src * 16 + j]);
            __half2 h0 = *(__half2*)&v.x, h1 = *(__half2*)&v.y;
            float2 f0 = __half22float2(h0), f1 = __half22float2(h1);
            acc.x += w * f0.x;
            acc.y += w * f0.y;
            acc.z += w * f1.x;
            acc.w += w * f1.y;
        }
    }
    // remainder (0..15 edges)
    int rem = pend - p;
    if (rem > 0) {
        int2 er = make_int2(0, 0);
        if (j < rem) er = __ldg(&g_edge[p + j]);
        for (int i = 0; i < rem; i++) {
            int src = __shfl_sync(gmask, er.x, i, 16);
            float w = __int_as_float(__shfl_sync(gmask, er.y, i, 16));
            uint2 v = __ldg(&hw2[src * 16 + j]);
            __half2 h0 = *(__half2*)&v.x, h1 = *(__half2*)&v.y;
            float2 f0 = __half22float2(h0), f1 = __half22float2(h1);
            acc.x += w * f0.x;
            acc.y += w * f0.y;
            acc.z += w * f1.x;
            acc.w += w * f1.y;
        }
    }

    float4 b = ((const float4*)bias)[j];
    acc.x += b.x; acc.y += b.y; acc.z += b.z; acc.w += b.w;

    // LayerNorm over 64 values (16 lanes x 4)
    float lsum = acc.x + acc.y + acc.z + acc.w;
    float lsq  = acc.x * acc.x + acc.y * acc.y + acc.z * acc.z + acc.w * acc.w;
#pragma unroll
    for (int m = 8; m >= 1; m >>= 1) {
        lsum += __shfl_xor_sync(gmask, lsum, m, 16);
        lsq  += __shfl_xor_sync(gmask, lsq,  m, 16);
    }
    float mean = lsum * (1.0f / 64.0f);
    float var = lsq * (1.0f / 64.0f) - mean * mean;
    float rstd = rsqrtf(var + EPS);

    float4 g = ((const float4*)gamma)[j];
    float4 be = ((const float4*)beta)[j];
    float4 o;
    o.x = (acc.x - mean) * rstd * g.x + be.x;
    o.y = (acc.y - mean) * rstd * g.y + be.y;
    o.z = (acc.z - mean) * rstd * g.z + be.z;
    o.w = (acc.w - mean) * rstd * g.w + be.w;
    if (do_relu) {
        o.x = fmaxf(o.x, 0.f);
        o.y = fmaxf(o.y, 0.f);
        o.z = fmaxf(o.z, 0.f);
        o.w = fmaxf(o.w, 0.f);
    }
    ((float4*)out)[node * 16 + j] = o;
}

// ---------------- launch ----------------
extern "C" void kernel_launch(void* const* d_in, const int* in_sizes, int n_in,
                              void* d_out, int out_size) {
    const float* x      = (const float*)d_in[0];   // (N, D)
    const float* Ws     = (const float*)d_in[1];   // (L, D, D)
    const float* bs     = (const float*)d_in[2];   // (L, D)
    const float* gammas = (const float*)d_in[3];   // (L, D)
    const float* betas  = (const float*)d_in[4];   // (L, D)
    const int*   ei     = (const int*)d_in[5];     // (2, E)
    float* outp = (float*)d_out;

    __half* d_hw;
    float*  d_h;
    cudaGetSymbolAddress((void**)&d_hw, g_hw);
    cudaGetSymbolAddress((void**)&d_h, g_h);

    const int TB = 256;
    const int gGemm = G_GEMM;
    const int gAgg = NN / 16;

    // fat kernel: layer-0 GEMM overlapped with edge counting (independent work)
    k_count_gemm0<<<G_GEMM + G_EDGE, TB>>>(ei, x, Ws + 0 * DD * DD, d_hw);
    // rest of CSR build
    k_bsum<<<NBLK, 256>>>();
    k_bscan<<<1, 128>>>();
    k_bscan_fill<<<NBLK, 256>>>();
    k_fill<<<G_EDGE, TB>>>(ei);

    // layer 0 agg (hw ready from fat kernel, CSR ready from k_fill)
    k_agg<<<gAgg, TB>>>(d_hw, bs + 0 * DD, gammas + 0 * DD, betas + 0 * DD, d_h, 1);
    // layer 1
    k_gemm<<<gGemm, TB>>>(d_h, Ws + 1 * DD * DD, d_hw);
    k_agg<<<gAgg, TB>>>(d_hw, bs + 1 * DD, gammas + 1 * DD, betas + 1 * DD, d_h, 1);
    // layer 2 (no relu)
    k_gemm<<<gGemm, TB>>>(d_h, Ws + 2 * DD * DD, d_hw);
    k_agg<<<gAgg, TB>>>(d_hw, bs + 2 * DD, gammas + 2 * DD, betas + 2 * DD, outp, 0);
}

// round 17
// speedup vs baseline: 1.2538x; 1.0078x over previous
#include <cuda_runtime.h>
#include <cuda_fp16.h>

#define NN 100000
#define EE 1600000
#define DD 64
#define EPS 1e-5f

#define NBLK 98                       // ceil(NN/1024)
#define NN_PAD (NBLK * 1024)          // 100352
#define G_GEMM 1563                   // ceil(NN/64)
#define G_EDGE 6250                   // EE/256
#define G_FAT  7815                   // 5 * G_GEMM: every 5th block is a gemm tile

// ---------------- device scratch (no allocations allowed) ----------------
__device__ __align__(16) int    g_deg[NN_PAD];     // zero-init; re-zeroed by k_bscan_fill each launch
__device__ __align__(16) float  g_dinv[NN_PAD];    // rsqrt(deg+1)
__device__ __align__(16) int    g_off[NN_PAD];     // CSR offsets
__device__ __align__(16) int    g_cursor[NN_PAD];  // fill cursors
__device__                int    g_bsum[NBLK];
__device__                int    g_bpre[NBLK];
__device__ __align__(8)  int2   g_edge[EE];        // (src, float-bits weight)
__device__ __align__(16) __half g_hw[NN * DD];     // h @ W buffer (fp16)
__device__ __align__(16) __half g_h[NN * DD];      // intermediate h buffer (fp16)

// ---------------- GEMM body (templated on input precision) ----------------
template <bool IN_HALF>
__device__ __forceinline__ void gemm_body(int blk, int t,
                                          const void* __restrict__ hin,
                                          const float* __restrict__ W,
                                          __half* __restrict__ hout,
                                          float4* sW, float (*sH)[68]) {
    const float4* W4 = (const float4*)W;
#pragma unroll
    for (int i = 0; i < 4; i++) sW[t + i * 256] = W4[t + i * 256];

    const int rowbase = blk * 64;
#pragma unroll
    for (int i = 0; i < 4; i++) {
        int idx = t + i * 256;          // 0..1023
        int r = idx >> 4, c = idx & 15;
        float4 v = make_float4(0.f, 0.f, 0.f, 0.f);
        if (rowbase + r < NN) {
            if (IN_HALF) {
                uint2 u = ((const uint2*)hin)[(rowbase + r) * 16 + c];
                float2 f0 = __half22float2(*(__half2*)&u.x);
                float2 f1 = __half22float2(*(__half2*)&u.y);
                v = make_float4(f0.x, f0.y, f1.x, f1.y);
            } else {
                v = ((const float4*)hin)[(rowbase + r) * 16 + c];
            }
        }
        ((float4*)&sH[r][0])[c] = v;
    }
    __syncthreads();

    const int j = t & 15;       // col group (4 cols)
    const int rg = t >> 4;      // rows rg, rg+16, rg+32, rg+48

    float4 a0 = make_float4(0.f, 0.f, 0.f, 0.f);
    float4 a1 = a0, a2 = a0, a3 = a0;
#pragma unroll 16
    for (int k = 0; k < 64; k++) {
        float4 w = sW[k * 16 + j];
        float h0 = sH[rg][k];
        float h1 = sH[rg + 16][k];
        float h2 = sH[rg + 32][k];
        float h3 = sH[rg + 48][k];
        a0.x += h0 * w.x; a0.y += h0 * w.y; a0.z += h0 * w.z; a0.w += h0 * w.w;
        a1.x += h1 * w.x; a1.y += h1 * w.y; a1.z += h1 * w.z; a1.w += h1 * w.w;
        a2.x += h2 * w.x; a2.y += h2 * w.y; a2.z += h2 * w.z; a2.w += h2 * w.w;
        a3.x += h3 * w.x; a3.y += h3 * w.y; a3.z += h3 * w.z; a3.w += h3 * w.w;
    }

    uint2* hout2 = (uint2*)hout;
    uint2 p;
    __half2 q0, q1;
    if (rowbase + rg < NN) {
        q0 = __floats2half2_rn(a0.x, a0.y); q1 = __floats2half2_rn(a0.z, a0.w);
        p.x = *(unsigned*)&q0; p.y = *(unsigned*)&q1;
        hout2[(rowbase + rg) * 16 + j] = p;
    }
    if (rowbase + rg + 16 < NN) {
        q0 = __floats2half2_rn(a1.x, a1.y); q1 = __floats2half2_rn(a1.z, a1.w);
        p.x = *(unsigned*)&q0; p.y = *(unsigned*)&q1;
        hout2[(rowbase + rg + 16) * 16 + j] = p;
    }
    if (rowbase + rg + 32 < NN) {
        q0 = __floats2half2_rn(a2.x, a2.y); q1 = __floats2half2_rn(a2.z, a2.w);
        p.x = *(unsigned*)&q0; p.y = *(unsigned*)&q1;
        hout2[(rowbase + rg + 32) * 16 + j] = p;
    }
    if (rowbase + rg + 48 < NN) {
        q0 = __floats2half2_rn(a3.x, a3.y); q1 = __floats2half2_rn(a3.z, a3.w);
        p.x = *(unsigned*)&q0; p.y = *(unsigned*)&q1;
        hout2[(rowbase + rg + 48) * 16 + j] = p;
    }
}

// ---- fat kernel: interleaved layer-0 GEMM (every 5th block) + edge-count ----
__global__ __launch_bounds__(256) void k_count_gemm0(const int* __restrict__ ei,
                                                     const float* __restrict__ x,
                                                     const float* __restrict__ W0,
                                                     __half* __restrict__ hw) {
    __shared__ float4 sW[64 * 16];
    __shared__ float  sH[64][68];
    const int t = threadIdx.x;
    const int bid = blockIdx.x;
    if (bid % 5 == 0) {
        gemm_body<false>(bid / 5, t, x, W0, hw, sW, sH);
    } else {
        int cidx = bid - bid / 5 - 1;          // 0..6251
        int e = cidx * 256 + t;
        if (e < EE) atomicAdd(&g_deg[ei[EE + e]], 1);
    }
}

// ---------------- standalone GEMM (layers 1,2; fp16 input) ----------------
__global__ __launch_bounds__(256) void k_gemm_h(const __half* __restrict__ hin,
                                                const float* __restrict__ W,
                                                __half* __restrict__ hout) {
    __shared__ float4 sW[64 * 16];
    __shared__ float  sH[64][68];
    gemm_body<true>(blockIdx.x, threadIdx.x, hin, W, hout, sW, sH);
}

// ---------------- CSR build ----------------
__global__ __launch_bounds__(256) void k_bsum() {
    const int t = threadIdx.x, b = blockIdx.x;
    const int4* d4 = (const int4*)g_deg;
    int4 v = d4[b * 256 + t];
    int s = v.x + v.y + v.z + v.w;
#pragma unroll
    for (int m = 16; m; m >>= 1) s += __shfl_xor_sync(0xffffffffu, s, m);
    __shared__ int ws[8];
    if ((t & 31) == 0) ws[t >> 5] = s;
    __syncthreads();
    if (t == 0) {
        int x = 0;
#pragma unroll
        for (int i = 0; i < 8; i++) x += ws[i];
        g_bsum[b] = x;
    }
}

__global__ __launch_bounds__(128) void k_bscan() {
    __shared__ int s[128];
    const int t = threadIdx.x;
    int v = (t < NBLK) ? g_bsum[t] : 0;
    s[t] = v;
    __syncthreads();
    for (int off = 1; off < 128; off <<= 1) {
        int u = (t >= off) ? s[t - off] : 0;
        __syncthreads();
        s[t] += u;
        __syncthreads();
    }
    if (t < NBLK) g_bpre[t] = s[t] - v;  // exclusive
}

// writes g_off, g_cursor, g_dinv; re-zeroes g_deg for the next launch
__global__ __launch_bounds__(256) void k_bscan_fill() {
    const int t = threadIdx.x, b = blockIdx.x;
    const int lane = t & 31, wid = t >> 5;
    const int4* d4 = (const int4*)g_deg;
    int4 c = d4[b * 256 + t];
    int sum4 = c.x + c.y + c.z + c.w;

    int inc = sum4;
#pragma unroll
    for (int m = 1; m < 32; m <<= 1) {
        int u = __shfl_up_sync(0xffffffffu, inc, m);
        if (lane >= m) inc += u;
    }
    __shared__ int wsum[8], wpre[8];
    if (lane == 31) wsum[wid] = inc;
    __syncthreads();
    if (t == 0) {
        int r = 0;
#pragma unroll
        for (int i = 0; i < 8; i++) { wpre[i] = r; r += wsum[i]; }
    }
    __syncthreads();

    int excl = inc - sum4 + wpre[wid] + g_bpre[b];
    int o0 = excl, o1 = o0 + c.x, o2 = o1 + c.y, o3 = o2 + c.z;
    int4 off4 = make_int4(o0, o1, o2, o3);
    ((int4*)g_off)[b * 256 + t] = off4;
    ((int4*)g_cursor)[b * 256 + t] = off4;
    float4 dv;
    dv.x = rsqrtf((float)(c.x + 1));
    dv.y = rsqrtf((float)(c.y + 1));
    dv.z = rsqrtf((float)(c.z + 1));
    dv.w = rsqrtf((float)(c.w + 1));
    ((float4*)g_dinv)[b * 256 + t] = dv;
    ((int4*)g_deg)[b * 256 + t] = make_int4(0, 0, 0, 0);  // reset for next replay
}

__global__ __launch_bounds__(256) void k_fill(const int* __restrict__ ei) {
    int e = blockIdx.x * blockDim.x + threadIdx.x;
    if (e < EE) {
        int r = ei[e];
        int c = ei[EE + e];
        int p = atomicAdd(&g_cursor[c], 1);
        float w = g_dinv[r] * g_dinv[c];
        g_edge[p] = make_int2(r, __float_as_int(w));
    }
}

// ---------------- fused aggregate + bias + LayerNorm (+ReLU) ----------------
// 16 lanes per node; fp16 gather (8B/lane); meta batches of 16, pipelined
__global__ __launch_bounds__(256) void k_agg(const __half* __restrict__ hw,
                                             const float* __restrict__ bias,
                                             const float* __restrict__ gamma,
                                             const float* __restrict__ beta,
                                             void* __restrict__ out,
                                             int do_relu, int out_half) {
    const int t = threadIdx.x;
    const int node = blockIdx.x * 16 + (t >> 4);   // NN % 16 == 0
    const int j = t & 15;
    const unsigned gmask = 0xffffu << (t & 16);

    const uint2* hw2 = (const uint2*)hw;

    // self-loop term
    float dn = g_dinv[node];
    uint2 sv = __ldg(&hw2[node * 16 + j]);
    float2 sf0 = __half22float2(*(__half2*)&sv.x);
    float2 sf1 = __half22float2(*(__half2*)&sv.y);
    float wself = dn * dn;
    float4 acc;
    acc.x = sf0.x * wself; acc.y = sf0.y * wself;
    acc.z = sf1.x * wself; acc.w = sf1.y * wself;

    int p = g_off[node];
    const int pend = g_off[node + 1];

    // pipelined full batches of 16 edges
    int2 e = make_int2(0, 0);
    bool have = (p + 16 <= pend);
    if (have) e = __ldg(&g_edge[p + j]);
    while (have) {
        int2 cur = e;
        p += 16;
        have = (p + 16 <= pend);
        if (have) e = __ldg(&g_edge[p + j]);   // prefetch next batch
#pragma unroll
        for (int i = 0; i < 16; i++) {
            int src = __shfl_sync(gmask, cur.x, i, 16);
            float w = __int_as_float(__shfl_sync(gmask, cur.y, i, 16));
            uint2 v = __ldg(&hw2[src * 16 + j]);
            float2 f0 = __half22float2(*(__half2*)&v.x);
            float2 f1 = __half22float2(*(__half2*)&v.y);
            acc.x += w * f0.x;
            acc.y += w * f0.y;
            acc.z += w * f1.x;
            acc.w += w * f1.y;
        }
    }
    // remainder (0..15 edges)
    int rem = pend - p;
    if (rem > 0) {
        int2 er = make_int2(0, 0);
        if (j < rem) er = __ldg(&g_edge[p + j]);
        for (int i = 0; i < rem; i++) {
            int src = __shfl_sync(gmask, er.x, i, 16);
            float w = __int_as_float(__shfl_sync(gmask, er.y, i, 16));
            uint2 v = __ldg(&hw2[src * 16 + j]);
            float2 f0 = __half22float2(*(__half2*)&v.x);
            float2 f1 = __half22float2(*(__half2*)&v.y);
            acc.x += w * f0.x;
            acc.y += w * f0.y;
            acc.z += w * f1.x;
            acc.w += w * f1.y;
        }
    }

    float4 b = ((const float4*)bias)[j];
    acc.x += b.x; acc.y += b.y; acc.z += b.z; acc.w += b.w;

    // LayerNorm over 64 values (16 lanes x 4)
    float lsum = acc.x + acc.y + acc.z + acc.w;
    float lsq  = acc.x * acc.x + acc.y * acc.y + acc.z * acc.z + acc.w * acc.w;
#pragma unroll
    for (int m = 8; m >= 1; m >>= 1) {
        lsum += __shfl_xor_sync(gmask, lsum, m, 16);
        lsq  += __shfl_xor_sync(gmask, lsq,  m, 16);
    }
    float mean = lsum * (1.0f / 64.0f);
    float var = lsq * (1.0f / 64.0f) - mean * mean;
    float rstd = rsqrtf(var + EPS);

    float4 g = ((const float4*)gamma)[j];
    float4 be = ((const float4*)beta)[j];
    float4 o;
    o.x = (acc.x - mean) * rstd * g.x + be.x;
    o.y = (acc.y - mean) * rstd * g.y + be.y;
    o.z = (acc.z - mean) * rstd * g.z + be.z;
    o.w = (acc.w - mean) * rstd * g.w + be.w;
    if (do_relu) {
        o.x = fmaxf(o.x, 0.f);
        o.y = fmaxf(o.y, 0.f);
        o.z = fmaxf(o.z, 0.f);
        o.w = fmaxf(o.w, 0.f);
    }
    if (out_half) {
        __half2 q0 = __floats2half2_rn(o.x, o.y);
        __half2 q1 = __floats2half2_rn(o.z, o.w);
        uint2 pk;
        pk.x = *(unsigned*)&q0; pk.y = *(unsigned*)&q1;
        ((uint2*)out)[node * 16 + j] = pk;
    } else {
        ((float4*)out)[node * 16 + j] = o;
    }
}

// ---------------- launch ----------------
extern "C" void kernel_launch(void* const* d_in, const int* in_sizes, int n_in,
                              void* d_out, int out_size) {
    const float* x      = (const float*)d_in[0];   // (N, D)
    const float* Ws     = (const float*)d_in[1];   // (L, D, D)
    const float* bs     = (const float*)d_in[2];   // (L, D)
    const float* gammas = (const float*)d_in[3];   // (L, D)
    const float* betas  = (const float*)d_in[4];   // (L, D)
    const int*   ei     = (const int*)d_in[5];     // (2, E)
    float* outp = (float*)d_out;

    __half* d_hw;
    __half* d_h;
    cudaGetSymbolAddress((void**)&d_hw, g_hw);
    cudaGetSymbolAddress((void**)&d_h, g_h);

    const int TB = 256;
    const int gAgg = NN / 16;

    // fat kernel: layer-0 GEMM interleaved with edge counting (independent work)
    k_count_gemm0<<<G_FAT, TB>>>(ei, x, Ws + 0 * DD * DD, d_hw);
    // rest of CSR build
    k_bsum<<<NBLK, 256>>>();
    k_bscan<<<1, 128>>>();
    k_bscan_fill<<<NBLK, 256>>>();
    k_fill<<<G_EDGE, TB>>>(ei);

    // layer 0 agg (hw ready from fat kernel, CSR ready from k_fill) -> fp16 h
    k_agg<<<gAgg, TB>>>(d_hw, bs + 0 * DD, gammas + 0 * DD, betas + 0 * DD, d_h, 1, 1);
    // layer 1
    k_gemm_h<<<G_GEMM, TB>>>(d_h, Ws + 1 * DD * DD, d_hw);
    k_agg<<<gAgg, TB>>>(d_hw, bs + 1 * DD, gammas + 1 * DD, betas + 1 * DD, d_h, 1, 1);
    // layer 2 (no relu) -> fp32 output
    k_gemm_h<<<G_GEMM, TB>>>(d_h, Ws + 2 * DD * DD, d_hw);
    k_agg<<<gAgg, TB>>>(d_hw, bs + 2 * DD, gammas + 2 * DD, betas + 2 * DD, outp, 0, 0);
}